// round 4
// baseline (speedup 1.0000x reference)
#include <cuda_runtime.h>
#include <math.h>

#define NPTS  32768
#define NQ    4096
#define BATCH 2
#define KNBR  32
#define EMBD  96
#define C0    128
#define C1    256
#define OUTC  128

// Scratch (no allocation allowed -> __device__ globals)
__device__ float g_A[BATCH * NPTS * C0];    // 32 MB: per-point layer0 partial
__device__ float g_Px[BATCH * NQ * C0];     // 4 MB : per-latent layer0 partial (+b0)
__device__ float g_bbox[BATCH * 6];         // min[3], max[3]

__device__ __forceinline__ float gelu_tanh(float x) {
    // matches jax.nn.gelu (approximate tanh form)
    float u = 0.7978845608028654f * (x + 0.044715f * x * x * x);
    return 0.5f * x * (1.0f + tanhf(u));
}

// freq_i = 10000^(-i/16), i in [0,16)
__device__ __forceinline__ float emb_entry(float coord, int r) {
    int i = r & 15;
    float freq = __expf(-(float)i * 0.5756462732485115f); // ln(10000)/16
    float a = coord * freq;
    return (r < 16) ? __sinf(a) : __cosf(a);
}

// ---------------------------------------------------------------------------
// bbox: per-batch coordinate min/max over 32768 points
// ---------------------------------------------------------------------------
__global__ void bbox_kernel(const float* __restrict__ gc) {
    int b = blockIdx.x;
    const float* p = gc + (size_t)b * NPTS * 3;
    float mn[3] = {1e30f, 1e30f, 1e30f};
    float mx[3] = {-1e30f, -1e30f, -1e30f};
    for (int i = threadIdx.x; i < NPTS; i += blockDim.x) {
        #pragma unroll
        for (int c = 0; c < 3; c++) {
            float v = p[i * 3 + c];
            mn[c] = fminf(mn[c], v);
            mx[c] = fmaxf(mx[c], v);
        }
    }
    #pragma unroll
    for (int o = 16; o > 0; o >>= 1) {
        #pragma unroll
        for (int c = 0; c < 3; c++) {
            mn[c] = fminf(mn[c], __shfl_xor_sync(0xffffffffu, mn[c], o));
            mx[c] = fmaxf(mx[c], __shfl_xor_sync(0xffffffffu, mx[c], o));
        }
    }
    __shared__ float s[8][6];
    int w = threadIdx.x >> 5;
    if ((threadIdx.x & 31) == 0) {
        #pragma unroll
        for (int c = 0; c < 3; c++) { s[w][c] = mn[c]; s[w][3 + c] = mx[c]; }
    }
    __syncthreads();
    if (threadIdx.x == 0) {
        #pragma unroll
        for (int c = 0; c < 3; c++) {
            float a = s[0][c], bb = s[0][3 + c];
            for (int i = 1; i < 8; i++) {
                a = fminf(a, s[i][c]);
                bb = fmaxf(bb, s[i][3 + c]);
            }
            g_bbox[b * 6 + c] = a;
            g_bbox[b * 6 + 3 + c] = bb;
        }
    }
}

// ---------------------------------------------------------------------------
// Px[b,q,:] = pos_embed(lat[b,q]) @ W0[96:192] + b0     (32 q per block)
// ---------------------------------------------------------------------------
__global__ void __launch_bounds__(128) px_kernel(const float* __restrict__ latent,
                                                 const float* __restrict__ W0,
                                                 const float* __restrict__ b0) {
    __shared__ float emb[32][EMBD];
    int blk = blockIdx.x;                 // 0 .. B*NQ/32-1
    int b = blk / (NQ / 32);
    int q0 = (blk % (NQ / 32)) * 32;
    int t = threadIdx.x;

    for (int idx = t; idx < 32 * EMBD; idx += 128) {
        int pt = idx / EMBD, e = idx % EMBD;
        int c = e >> 5, r = e & 31;
        float bmn = g_bbox[b * 6 + c], bmx = g_bbox[b * 6 + 3 + c];
        float coord = bmn + (bmx - bmn) * latent[(q0 + pt) * 3 + c];
        emb[pt][e] = emb_entry(coord, r);
    }
    __syncthreads();

    float acc[32];
    float bias = b0[t];
    #pragma unroll
    for (int p = 0; p < 32; p++) acc[p] = bias;
    for (int e = 0; e < EMBD; e++) {
        float w = W0[(96 + e) * C0 + t];
        #pragma unroll
        for (int p = 0; p < 32; p++) acc[p] += emb[p][e] * w;
    }
    float* dst = g_Px + ((size_t)(b * NQ + q0)) * C0 + t;
    #pragma unroll
    for (int p = 0; p < 32; p++) dst[p * C0] = acc[p];
}

// ---------------------------------------------------------------------------
// A[b,j,:] = pos_embed(y[j]) @ W0[0:96] + f[b,j] @ W0[192:196]  (32 pts/block)
// ---------------------------------------------------------------------------
__global__ void __launch_bounds__(128) a_kernel(const float* __restrict__ x,
                                                const float* __restrict__ gc,
                                                const float* __restrict__ W0) {
    __shared__ float emb[32][EMBD];
    __shared__ float ff[32][4];
    int blk = blockIdx.x;                  // 0 .. B*NPTS/32-1
    int b = blk / (NPTS / 32);
    int j0 = (blk % (NPTS / 32)) * 32;
    int t = threadIdx.x;

    for (int idx = t; idx < 32 * EMBD; idx += 128) {
        int pt = idx / EMBD, e = idx % EMBD;
        int c = e >> 5, r = e & 31;
        float coord = gc[((size_t)(b * NPTS) + j0 + pt) * 3 + c];
        emb[pt][e] = emb_entry(coord, r);
    }
    {   // f[b, j, c] = x[0, b, c, d, h, w], j = (h*32+w)*32+d
        int pt = t >> 2, c = t & 3;
        int j = j0 + pt;
        int d = j & 31, w = (j >> 5) & 31, h = j >> 10;
        ff[pt][c] = x[(size_t)(b * 4 + c) * NPTS + (size_t)d * 1024 + h * 32 + w];
    }
    __syncthreads();

    float acc[32];
    #pragma unroll
    for (int p = 0; p < 32; p++) acc[p] = 0.0f;
    for (int e = 0; e < EMBD; e++) {
        float w = W0[e * C0 + t];
        #pragma unroll
        for (int p = 0; p < 32; p++) acc[p] += emb[p][e] * w;
    }
    #pragma unroll
    for (int e = 0; e < 4; e++) {
        float w = W0[(192 + e) * C0 + t];
        #pragma unroll
        for (int p = 0; p < 32; p++) acc[p] += ff[p][e] * w;
    }
    float* dst = g_A + ((size_t)(b * NPTS + j0)) * C0 + t;
    #pragma unroll
    for (int p = 0; p < 32; p++) dst[p * C0] = acc[p];
}

// ---------------------------------------------------------------------------
// Main fused kernel: one block per (b,q). 32 rows through layers 1..3.
// Single 8192-float dynamic smem buffer, time-multiplexed:
//   phase A: h0 = gelu(gather(A) + Px)   in buf[0:4096]
//   phase B: h1 = gelu(h0 @ W1 + b1)     in buf[0:8192]  (h0 dead)
//   phase C: h2 = gelu(h1 @ W2 + b2)     in buf[0:4096]  (h1 dead)
//   phase D: hsum = sum_k mask_k h2_k    in buf[4096:4224]
//   out = hsum @ W3 + nvalid * b3
// ---------------------------------------------------------------------------
__global__ void __launch_bounds__(256) main_kernel(const int* __restrict__ nbr_idx,
                                                   const unsigned int* __restrict__ nbr_mask,
                                                   const float* __restrict__ W1, const float* __restrict__ b1,
                                                   const float* __restrict__ W2, const float* __restrict__ b2,
                                                   const float* __restrict__ W3, const float* __restrict__ b3,
                                                   float* __restrict__ out) {
    extern __shared__ float buf[];        // 8192 floats = 32 KB
    __shared__ int   sidx[KNBR];
    __shared__ float smsk[KNBR];

    int blk = blockIdx.x;
    int b = blk >> 12;
    int q = blk & 4095;
    int t = threadIdx.x;

    if (t < KNBR) {
        int base = (b * NQ + q) * KNBR + t;
        sidx[t] = nbr_idx[base];
        // mask serialized as a 4-byte type (int32 0/1 OR float32 0.0/1.0):
        // in both encodings, "true" <=> nonzero 32-bit word.
        smsk[t] = (nbr_mask[base] != 0u) ? 1.0f : 0.0f;
    }
    __syncthreads();

    // ---- phase A: h0 = gelu(gather + Px) ----
    const float* Px = g_Px + ((size_t)(b * NQ + q)) * C0;
    #pragma unroll
    for (int r = 0; r < 16; r++) {
        int lin = t + (r << 8);
        int k = lin >> 7, c = lin & 127;
        float v = g_A[((size_t)(b * NPTS + sidx[k])) * C0 + c] + Px[c];
        buf[lin] = gelu_tanh(v);
    }
    __syncthreads();

    // ---- phase B: h1 = gelu(h0 @ W1 + b1); col = t (0..255), all 32 rows ----
    {
        float acc[32];
        float bias = b1[t];
        #pragma unroll
        for (int k = 0; k < 32; k++) acc[k] = bias;
        #pragma unroll 2
        for (int j = 0; j < 128; j += 4) {
            float w0 = W1[(j + 0) * C1 + t];
            float w1 = W1[(j + 1) * C1 + t];
            float w2 = W1[(j + 2) * C1 + t];
            float w3 = W1[(j + 3) * C1 + t];
            #pragma unroll
            for (int k = 0; k < 32; k++) {
                float4 h = *(const float4*)(buf + k * 128 + j);
                acc[k] += h.x * w0;
                acc[k] += h.y * w1;
                acc[k] += h.z * w2;
                acc[k] += h.w * w3;
            }
        }
        __syncthreads();   // all h0 reads done before h1 overwrites buf
        #pragma unroll
        for (int k = 0; k < 32; k++) buf[k * 256 + t] = gelu_tanh(acc[k]);
    }
    __syncthreads();

    // ---- phase C: h2 = gelu(h1 @ W2 + b2); col = t&127, 16 rows per half ----
    {
        int c = t & 127;
        int k0 = (t >> 7) * 16;
        float acc[16];
        float bias = b2[c];
        #pragma unroll
        for (int k = 0; k < 16; k++) acc[k] = bias;
        #pragma unroll 2
        for (int j = 0; j < 256; j += 4) {
            float w0 = W2[(j + 0) * C0 + c];
            float w1 = W2[(j + 1) * C0 + c];
            float w2 = W2[(j + 2) * C0 + c];
            float w3 = W2[(j + 3) * C0 + c];
            #pragma unroll
            for (int k = 0; k < 16; k++) {
                float4 h = *(const float4*)(buf + (k0 + k) * 256 + j);
                acc[k] += h.x * w0;
                acc[k] += h.y * w1;
                acc[k] += h.z * w2;
                acc[k] += h.w * w3;
            }
        }
        __syncthreads();   // all h1 reads done before h2 overwrites buf
        #pragma unroll
        for (int k = 0; k < 16; k++) buf[(k0 + k) * 128 + c] = gelu_tanh(acc[k]);
    }
    __syncthreads();

    // ---- phase D: masked row-sum of h2 into buf[4096:4224] ----
    if (t < 128) {
        float s = 0.0f;
        #pragma unroll
        for (int k = 0; k < 32; k++) s += smsk[k] * buf[k * 128 + t];
        buf[4096 + t] = s;
    }
    __syncthreads();

    // ---- out = hsum @ W3 + nvalid * b3 ----
    if (t < 128) {
        float nv = 0.0f;
        #pragma unroll
        for (int k = 0; k < 32; k++) nv += smsk[k];
        float acc = nv * b3[t];
        #pragma unroll 4
        for (int j = 0; j < 128; j++) acc += buf[4096 + j] * W3[j * C0 + t];
        // out layout (T=1, B, C=128, Dl, Hl, Wl); q = (hl*16+wl)*16+dl
        int dl = q & 15, wl = (q >> 4) & 15, hl = q >> 8;
        out[((((size_t)b * 128 + t) * 16 + dl) * 16 + hl) * 16 + wl] = acc;
    }
}

extern "C" void kernel_launch(void* const* d_in, const int* in_sizes, int n_in,
                              void* d_out, int out_size) {
    const float* x        = (const float*)d_in[0];
    const float* gc       = (const float*)d_in[1];
    const float* latent   = (const float*)d_in[2];
    const int*   nbr_idx  = (const int*)d_in[3];
    const unsigned int* nbr_mask = (const unsigned int*)d_in[4];
    const float* W0 = (const float*)d_in[5];
    const float* b0 = (const float*)d_in[6];
    const float* W1 = (const float*)d_in[7];
    const float* b1 = (const float*)d_in[8];
    const float* W2 = (const float*)d_in[9];
    const float* b2 = (const float*)d_in[10];
    const float* W3 = (const float*)d_in[11];
    const float* b3 = (const float*)d_in[12];
    float* out = (float*)d_out;

    bbox_kernel<<<BATCH, 256>>>(gc);
    px_kernel<<<BATCH * NQ / 32, 128>>>(latent, W0, b0);
    a_kernel<<<BATCH * NPTS / 32, 128>>>(x, gc, W0);

    size_t smem = 8192 * sizeof(float);   // 32 KB dynamic, well under 48 KB cap
    main_kernel<<<BATCH * NQ, 256, smem>>>(nbr_idx, nbr_mask,
                                           W1, b1, W2, b2, W3, b3, out);
}